// round 17
// baseline (speedup 1.0000x reference)
#include <cuda_runtime.h>
#include <cuda_fp16.h>
#include <math.h>
#include <stdint.h>

#define DIM   1024
#define BT    2
#define NT    2048
#define HEADS 16
#define HD    64
#define MLPD  4096
#define ROWS  (BT*NT)

typedef __half h16;

// ---------------------------------------------------------------------------
// Scratch (static device globals)
// ---------------------------------------------------------------------------
__device__ float g_mod [BT*6*DIM];
__device__ __align__(16) h16 g_xn  [ROWS*DIM];
__device__ __align__(16) h16 g_q   [ROWS*DIM];
__device__ __align__(16) h16 g_k   [ROWS*DIM];
__device__ __align__(16) h16 g_v   [ROWS*DIM];
__device__ __align__(16) h16 g_attn[ROWS*DIM];
__device__ __align__(16) h16 g_h   [(size_t)ROWS*MLPD];
// fp16 weights, transposed to [N][K]: QKV (3M), Wo (1M), W1 (4M), W2 (4M)
__device__ __align__(16) h16 g_wt  [12*1024*1024];

#define W_O (3*1024*1024)
#define W_1 (4*1024*1024)
#define W_2 (8*1024*1024)

// ---------------------------------------------------------------------------
// PTX helpers
// ---------------------------------------------------------------------------
__device__ __forceinline__ uint32_t smaddr(const void* p){
    return (uint32_t)__cvta_generic_to_shared(p);
}
__device__ __forceinline__ void cp16(uint32_t d, const void* s){
    asm volatile("cp.async.cg.shared.global [%0], [%1], 16;\n" :: "r"(d), "l"(s));
}
__device__ __forceinline__ void cp_commit(){
    asm volatile("cp.async.commit_group;\n" ::);
}
__device__ __forceinline__ void cp_wait1(){
    asm volatile("cp.async.wait_group 1;\n" ::);
}
// D(16x8,f32) += A(16x16 f16, row) * B(16x8 f16, col)
__device__ __forceinline__ void mma_h(float* c, const uint32_t* a, const uint32_t* b){
    asm volatile(
        "mma.sync.aligned.m16n8k16.row.col.f32.f16.f16.f32 "
        "{%0,%1,%2,%3}, {%4,%5,%6,%7}, {%8,%9}, {%0,%1,%2,%3};\n"
        : "+f"(c[0]), "+f"(c[1]), "+f"(c[2]), "+f"(c[3])
        : "r"(a[0]), "r"(a[1]), "r"(a[2]), "r"(a[3]),
          "r"(b[0]), "r"(b[1]));
}
// 4x 8x8 b16 matrices; lane l supplies row (l&7) of matrix (l>>3)
__device__ __forceinline__ void ldsm4(uint32_t* r, uint32_t addr){
    asm volatile("ldmatrix.sync.aligned.m8n8.x4.shared.b16 {%0,%1,%2,%3}, [%4];"
        : "=r"(r[0]), "=r"(r[1]), "=r"(r[2]), "=r"(r[3]) : "r"(addr));
}

// ---------------------------------------------------------------------------
// 0) ONE fused weight prepass: fp32 W[K][N] -> fp16 Wt[N][K] for all 6 mats
// ---------------------------------------------------------------------------
__global__ void __launch_bounds__(256) trans_all(
    const float* __restrict__ Wq, const float* __restrict__ Wk,
    const float* __restrict__ Wv, const float* __restrict__ Wo,
    const float* __restrict__ W1, const float* __restrict__ W2,
    h16* __restrict__ wt)
{
    __shared__ float t[32][33];
    int bid = blockIdx.x;
    const float* src; h16* dst; int K, N, kb, nb;
    if (bid < 4096) {
        int m = bid >> 10, tile = bid & 1023;
        src = (m==0)?Wq:(m==1)?Wk:(m==2)?Wv:Wo;
        dst = wt + (size_t)m*1024*1024;
        K = 1024; N = 1024;
        kb = (tile >> 5)*32; nb = (tile & 31)*32;
    } else if (bid < 8192) {
        int tile = bid - 4096;
        src = W1; dst = wt + W_1; K = 1024; N = 4096;
        kb = (tile >> 7)*32; nb = (tile & 127)*32;
    } else {
        int tile = bid - 8192;
        src = W2; dst = wt + W_2; K = 4096; N = 1024;
        kb = (tile >> 5)*32; nb = (tile & 31)*32;
    }
    int tx = threadIdx.x & 31, ty = threadIdx.x >> 5;
    #pragma unroll
    for (int j = 0; j < 32; j += 8)
        t[ty+j][tx] = src[(size_t)(kb+ty+j)*N + nb + tx];
    __syncthreads();
    #pragma unroll
    for (int j = 0; j < 32; j += 8)
        dst[(size_t)(nb+ty+j)*K + kb + tx] = __float2half(t[tx][ty+j]);
}

// ---------------------------------------------------------------------------
// 1) mod = silu(t_emb) @ ada_W + ada_b
// ---------------------------------------------------------------------------
__global__ void __launch_bounds__(256) silu_mod_kernel(
    const float* __restrict__ t_emb, const float* __restrict__ adaW,
    const float* __restrict__ adab, float* __restrict__ mod)
{
    __shared__ float st[DIM];
    int b = blockIdx.y;
    int j = blockIdx.x * 256 + threadIdx.x;
    for (int i = threadIdx.x; i < DIM; i += 256) {
        float t = t_emb[b*DIM + i];
        st[i] = t / (1.f + __expf(-t));
    }
    __syncthreads();
    float acc = 0.f;
    #pragma unroll 4
    for (int kk = 0; kk < DIM; kk++)
        acc += st[kk] * adaW[(size_t)kk*6*DIM + j];
    mod[b*6*DIM + j] = acc + adab[j];
}

// ---------------------------------------------------------------------------
// 2) LN + adaLN modulation -> fp16
// ---------------------------------------------------------------------------
__global__ void __launch_bounds__(256) ln_mod_kernel(
    const float* __restrict__ x, h16* __restrict__ out,
    const float* __restrict__ g, const float* __restrict__ bb,
    const float* __restrict__ mod, int shift_chunk, int scale_chunk)
{
    int row = blockIdx.x;
    int b   = row >> 11;
    int tid = threadIdx.x;
    const float* xr = x + (size_t)row*DIM;
    float4 xv = *(const float4*)(xr + tid*4);
    float s  = xv.x + xv.y + xv.z + xv.w;
    float s2 = xv.x*xv.x + xv.y*xv.y + xv.z*xv.z + xv.w*xv.w;
    #pragma unroll
    for (int o = 16; o > 0; o >>= 1) {
        s  += __shfl_xor_sync(0xffffffffu, s,  o);
        s2 += __shfl_xor_sync(0xffffffffu, s2, o);
    }
    __shared__ float ws[8], ws2[8];
    __shared__ float smu, srstd;
    int wid = tid >> 5;
    if ((tid & 31) == 0) { ws[wid] = s; ws2[wid] = s2; }
    __syncthreads();
    if (tid == 0) {
        float S = 0.f, S2 = 0.f;
        #pragma unroll
        for (int i = 0; i < 8; i++) { S += ws[i]; S2 += ws2[i]; }
        float mu  = S  * (1.f/DIM);
        float var = S2 * (1.f/DIM) - mu*mu;
        smu = mu; srstd = rsqrtf(var + 1e-5f);
    }
    __syncthreads();
    float mu = smu, rstd = srstd;
    int c = tid*4;
    const float* mb = mod + b*6*DIM;
    float4 gv = *(const float4*)(g  + c);
    float4 bv = *(const float4*)(bb + c);
    float4 sc = *(const float4*)(mb + scale_chunk*DIM + c);
    float4 sh = *(const float4*)(mb + shift_chunk*DIM + c);
    float y0 = ((xv.x-mu)*rstd*gv.x + bv.x)*(1.f+sc.x) + sh.x;
    float y1 = ((xv.y-mu)*rstd*gv.y + bv.y)*(1.f+sc.y) + sh.y;
    float y2 = ((xv.z-mu)*rstd*gv.z + bv.z)*(1.f+sc.z) + sh.z;
    float y3 = ((xv.w-mu)*rstd*gv.w + bv.w)*(1.f+sc.w) + sh.w;
    h16* o = out + (size_t)row*DIM + c;
    *(__half2*)o       = __floats2half2_rn(y0, y1);
    *(__half2*)(o + 2) = __floats2half2_rn(y2, y3);
}

// ---------------------------------------------------------------------------
// fp16 GEMM v3: BM=BN=128, BK=64; 128 threads = 4 warps (2M x 2N);
//   warp tile 64x64; fragments via ldmatrix.x4 (8 LDSM per k-step vs 32 LDS).
//   2 CTAs/SM. EPI: 0 = QKV fp16, 1 = GELU fp16, 2 = res+gate fp32.
// ---------------------------------------------------------------------------
#define GTILE (128*72)
#define GBUF  (2*GTILE)
#define GBUF_BYTES (GBUF*2)
#define G_SMEM_BYTES (2*GBUF_BYTES)

template<int EPI>
__global__ void __launch_bounds__(128, 2) gemm_h(
    const h16* __restrict__ A, const h16* __restrict__ Wt,
    int K, int Nc,
    h16* __restrict__ o16a, h16* __restrict__ o16b, h16* __restrict__ o16c,
    float* __restrict__ ofp,
    const float* __restrict__ gate, const float* __restrict__ res)
{
    extern __shared__ h16 smh[];
    const int tid  = threadIdx.x;
    const int lane = tid & 31, warp = tid >> 5;
    const int grp  = lane >> 2, tig = lane & 3;
    const int wm   = warp & 1,  wn  = warp >> 1;   // 2 x 2 warps
    const int m0   = blockIdx.y * 128;
    const int n0g  = blockIdx.x * 128;
    const uint32_t smb = smaddr(smh);
    const int nk = K >> 6;

    // ldmatrix lane geometry: matrix j = lane>>3, row-in-matrix rw = lane&7
    const int jj  = lane >> 3, rw = lane & 7;
    const int kof = (jj >> 1) * 8;                  // k offset for matrices 2,3
    const int lra = (wm*64 + (jj & 1)*8 + rw);      // A row (+ ma*16)
    const int lrb = (wn*64 + (jj & 1)*8 + rw);      // B row (+ nbp*16)

    float acc[4][8][4];
    #pragma unroll
    for (int i = 0; i < 4; i++)
        #pragma unroll
        for (int j = 0; j < 8; j++)
            #pragma unroll
            for (int t = 0; t < 4; t++) acc[i][j][t] = 0.f;

    auto prefetch = [&](int kc, int bufi){
        uint32_t base = smb + bufi*GBUF_BYTES;
        #pragma unroll
        for (int i = 0; i < 8; i++) {
            int idx = tid + i*128;
            int r = idx >> 3, c8 = (idx & 7) * 8;
            cp16(base + (uint32_t)(r*72 + c8)*2u,
                 A + (size_t)(m0 + r)*K + kc*64 + c8);
        }
        #pragma unroll
        for (int i = 0; i < 8; i++) {
            int idx = tid + i*128;
            int r = idx >> 3, c8 = (idx & 7) * 8;
            cp16(base + (uint32_t)(GTILE + r*72 + c8)*2u,
                 Wt + (size_t)(n0g + r)*K + kc*64 + c8);
        }
        cp_commit();
    };

    prefetch(0, 0);
    if (nk > 1) prefetch(1, 1); else cp_commit();

    int buf = 0;
    for (int kc = 0; kc < nk; kc++) {
        cp_wait1();
        __syncthreads();
        uint32_t ab = smb + buf*GBUF_BYTES;
        uint32_t bb_ = ab + GTILE*2;
        #pragma unroll
        for (int kk = 0; kk < 64; kk += 16) {
            uint32_t a[4][4], b[8][2];
            #pragma unroll
            for (int ma = 0; ma < 4; ma++)
                ldsm4(a[ma], ab + (uint32_t)((lra + ma*16)*72 + kk + kof)*2u);
            #pragma unroll
            for (int nbp = 0; nbp < 4; nbp++) {
                uint32_t t4[4];
                ldsm4(t4, bb_ + (uint32_t)((lrb + nbp*16)*72 + kk + kof)*2u);
                b[2*nbp  ][0] = t4[0]; b[2*nbp+1][0] = t4[1];
                b[2*nbp  ][1] = t4[2]; b[2*nbp+1][1] = t4[3];
            }
            #pragma unroll
            for (int ma = 0; ma < 4; ma++)
                #pragma unroll
                for (int nb = 0; nb < 8; nb++)
                    mma_h(acc[ma][nb], a[ma], b[nb]);
        }
        __syncthreads();
        if (kc + 2 < nk) prefetch(kc + 2, buf);
        else cp_commit();
        buf ^= 1;
    }

    #pragma unroll
    for (int ma = 0; ma < 4; ma++) {
        int r0 = m0 + wm*64 + ma*16 + grp;
        #pragma unroll
        for (int nb = 0; nb < 8; nb++) {
            int cl = wn*64 + nb*8 + 2*tig;
            float o0 = acc[ma][nb][0], o1 = acc[ma][nb][1];
            float o2 = acc[ma][nb][2], o3 = acc[ma][nb][3];
            if (EPI == 0) {
                int mat = blockIdx.x >> 3;
                h16* O = (mat == 0) ? o16a : (mat == 1) ? o16b : o16c;
                int c = ((blockIdx.x & 7) * 128) + cl;
                *(__half2*)(O + (size_t)r0    *DIM + c) = __floats2half2_rn(o0, o1);
                *(__half2*)(O + (size_t)(r0+8)*DIM + c) = __floats2half2_rn(o2, o3);
            } else if (EPI == 1) {
                int c = n0g + cl;
                o0 = 0.5f*o0*(1.f + erff(o0*0.70710678f));
                o1 = 0.5f*o1*(1.f + erff(o1*0.70710678f));
                o2 = 0.5f*o2*(1.f + erff(o2*0.70710678f));
                o3 = 0.5f*o3*(1.f + erff(o3*0.70710678f));
                *(__half2*)(o16a + (size_t)r0    *Nc + c) = __floats2half2_rn(o0, o1);
                *(__half2*)(o16a + (size_t)(r0+8)*Nc + c) = __floats2half2_rn(o2, o3);
            } else {
                int c = n0g + cl;
                int bi = r0 >> 11;
                float2 g2 = *(const float2*)(gate + bi*6*DIM + c);
                float2 ra = *(const float2*)(res + (size_t)r0    *Nc + c);
                float2 rb = *(const float2*)(res + (size_t)(r0+8)*Nc + c);
                o0 = ra.x + g2.x*o0; o1 = ra.y + g2.y*o1;
                o2 = rb.x + g2.x*o2; o3 = rb.y + g2.y*o3;
                *(float2*)(ofp + (size_t)r0    *Nc + c) = make_float2(o0, o1);
                *(float2*)(ofp + (size_t)(r0+8)*Nc + c) = make_float2(o2, o3);
            }
        }
    }
}

// ---------------------------------------------------------------------------
// 4) RoPE on fp16 q,k (fp32 math inside)
// ---------------------------------------------------------------------------
__global__ void __launch_bounds__(256) rope_kernel(h16* __restrict__ q,
                                                   h16* __restrict__ k)
{
    int idx = blockIdx.x*256 + threadIdx.x;
    int n = (idx >> 4) & (NT-1);
    float cs[32], sn[32];
    #pragma unroll
    for (int j = 0; j < 32; j++) {
        float invf = expf((float)j * -0.2878231366f);
        float ang  = (float)n * invf;
        sincosf(ang, &sn[j], &cs[j]);
    }
    h16* ptrs[2]; ptrs[0] = q + (size_t)idx*64; ptrs[1] = k + (size_t)idx*64;
    #pragma unroll
    for (int tpi = 0; tpi < 2; tpi++) {
        h16* p = ptrs[tpi];
        float buf[64];
        #pragma unroll
        for (int u = 0; u < 16; u++) {
            __half2 t = *(const __half2*)(p + u*4);
            __half2 t2 = *(const __half2*)(p + u*4 + 2);
            float2 f = __half22float2(t), f2 = __half22float2(t2);
            buf[u*4+0] = f.x;  buf[u*4+1] = f.y;
            buf[u*4+2] = f2.x; buf[u*4+3] = f2.y;
        }
        #pragma unroll
        for (int t = 0; t < 8; t++) {
            float l0 = buf[4*t+0]*cs[4*t+0] - buf[8*t+1]*sn[4*t+0];
            float l1 = buf[4*t+1]*cs[4*t+1] - buf[8*t+3]*sn[4*t+1];
            float l2 = buf[4*t+2]*cs[4*t+2] - buf[8*t+5]*sn[4*t+2];
            float l3 = buf[4*t+3]*cs[4*t+3] - buf[8*t+7]*sn[4*t+3];
            float h0 = buf[32+4*t+0]*cs[4*t+0] + buf[8*t+0]*sn[4*t+0];
            float h1 = buf[32+4*t+1]*cs[4*t+1] + buf[8*t+2]*sn[4*t+1];
            float h2 = buf[32+4*t+2]*cs[4*t+2] + buf[8*t+4]*sn[4*t+2];
            float h3 = buf[32+4*t+3]*cs[4*t+3] + buf[8*t+6]*sn[4*t+3];
            *(__half2*)(p + 4*t)          = __floats2half2_rn(l0, l1);
            *(__half2*)(p + 4*t + 2)      = __floats2half2_rn(l2, l3);
            *(__half2*)(p + 32 + 4*t)     = __floats2half2_rn(h0, h1);
            *(__half2*)(p + 32 + 4*t + 2) = __floats2half2_rn(h2, h3);
        }
    }
}

// ---------------------------------------------------------------------------
// 5) Flash v4: Q tile 256, 8 warps x 32 rows; fragments via ldmatrix.
// ---------------------------------------------------------------------------
#define FQ3 0
#define FK3 (256*72)
#define FV3 (FK3 + 64*72)
#define FP3 (FV3 + 64*72)
#define F3_SMEM_BYTES ((FP3 + 256*72)*2)

__global__ void __launch_bounds__(256) flash_h(
    const h16* __restrict__ q, const h16* __restrict__ k,
    const h16* __restrict__ v, h16* __restrict__ o)
{
    extern __shared__ h16 smh[];
    h16* Qs = smh + FQ3;
    h16* Ks = smh + FK3;
    h16* Vt = smh + FV3;
    h16* Ps = smh + FP3;
    const uint32_t smb = smaddr(smh);

    const int qt = blockIdx.x, bh = blockIdx.y;
    const int b = bh >> 4, h = bh & 15;
    const int tid = threadIdx.x;
    const int lane = tid & 31, warp = tid >> 5;
    const int grp = lane >> 2, tig = lane & 3;
    const int wrow = warp * 32;
    const h16* qb = q + (size_t)b*NT*DIM + h*HD;
    const h16* kb = k + (size_t)b*NT*DIM + h*HD;
    const h16* vb = v + (size_t)b*NT*DIM + h*HD;

    const int jj  = lane >> 3, rw = lane & 7;
    const int kof = (jj >> 1) * 8;
    const int lr  = (jj & 1)*8 + rw;     // row-in-16-block for ldmatrix

    const __half2 mk = __floats2half2_rn(0.125f, 0.125f);
    #pragma unroll
    for (int i = 0; i < 8; i++) {
        int idx = tid + i*256;
        int r = idx >> 3, c8 = (idx & 7) * 8;
        uint4 u = *(const uint4*)(qb + (size_t)(qt*256 + r)*DIM + c8);
        __half2* hp = (__half2*)&u;
        hp[0] = __hmul2(hp[0], mk); hp[1] = __hmul2(hp[1], mk);
        hp[2] = __hmul2(hp[2], mk); hp[3] = __hmul2(hp[3], mk);
        *(uint4*)&Qs[r*72 + c8] = u;
    }

    uint4 kr[2], vr[2];
    auto ldkv = [&](int kt){
        #pragma unroll
        for (int i = 0; i < 2; i++) {
            int idx = tid + i*256;
            int r = idx >> 3, c8 = (idx & 7) * 8;
            kr[i] = *(const uint4*)(kb + (size_t)(kt*64 + r)*DIM + c8);
            vr[i] = *(const uint4*)(vb + (size_t)(kt*64 + r)*DIM + c8);
        }
    };
    auto stkv = [&](){
        #pragma unroll
        for (int i = 0; i < 2; i++) {
            int idx = tid + i*256;
            int r = idx >> 3, c8 = (idx & 7) * 8;
            *(uint4*)&Ks[r*72 + c8] = kr[i];
            const h16* t = (const h16*)&vr[i];
            #pragma unroll
            for (int u8 = 0; u8 < 8; u8++)
                Vt[(c8+u8)*72 + r] = t[u8];
        }
    };

    float O[2][8][4];
    #pragma unroll
    for (int m2 = 0; m2 < 2; m2++)
        #pragma unroll
        for (int i = 0; i < 8; i++)
            #pragma unroll
            for (int j = 0; j < 4; j++) O[m2][i][j] = 0.f;
    float mM[2][2], lL[2][2];
    #pragma unroll
    for (int m2 = 0; m2 < 2; m2++) {
        mM[m2][0] = -1e30f; mM[m2][1] = -1e30f;
        lL[m2][0] = 0.f;    lL[m2][1] = 0.f;
    }

    ldkv(0);
    for (int kt = 0; kt < NT/64; kt++) {
        __syncthreads();
        stkv();
        __syncthreads();
        if (kt + 1 < NT/64) ldkv(kt + 1);

        // S = Q @ K^T
        float s[2][8][4];
        #pragma unroll
        for (int m2 = 0; m2 < 2; m2++)
            #pragma unroll
            for (int i = 0; i < 8; i++)
                #pragma unroll
                for (int j = 0; j < 4; j++) s[m2][i][j] = 0.f;
        #pragma unroll
        for (int kk = 0; kk < 64; kk += 16) {
            uint32_t bb[8][2];
            #pragma unroll
            for (int nbp = 0; nbp < 4; nbp++) {
                uint32_t t4[4];
                ldsm4(t4, smb + (uint32_t)(FK3 + (nbp*16 + lr)*72 + kk + kof)*2u);
                bb[2*nbp  ][0] = t4[0]; bb[2*nbp+1][0] = t4[1];
                bb[2*nbp  ][1] = t4[2]; bb[2*nbp+1][1] = t4[3];
            }
            #pragma unroll
            for (int m2 = 0; m2 < 2; m2++) {
                uint32_t a[4];
                ldsm4(a, smb + (uint32_t)(FQ3 + (wrow + m2*16 + lr)*72 + kk + kof)*2u);
                #pragma unroll
                for (int nb = 0; nb < 8; nb++)
                    mma_h(s[m2][nb], a, bb[nb]);
            }
        }

        // online softmax per m-block
        #pragma unroll
        for (int m2 = 0; m2 < 2; m2++) {
            float mx0 = -1e30f, mx1 = -1e30f;
            #pragma unroll
            for (int nb = 0; nb < 8; nb++) {
                mx0 = fmaxf(mx0, fmaxf(s[m2][nb][0], s[m2][nb][1]));
                mx1 = fmaxf(mx1, fmaxf(s[m2][nb][2], s[m2][nb][3]));
            }
            mx0 = fmaxf(mx0, __shfl_xor_sync(0xffffffffu, mx0, 1));
            mx0 = fmaxf(mx0, __shfl_xor_sync(0xffffffffu, mx0, 2));
            mx1 = fmaxf(mx1, __shfl_xor_sync(0xffffffffu, mx1, 1));
            mx1 = fmaxf(mx1, __shfl_xor_sync(0xffffffffu, mx1, 2));
            float nm0 = fmaxf(mM[m2][0], mx0), nm1 = fmaxf(mM[m2][1], mx1);
            float a0 = __expf(mM[m2][0] - nm0), a1 = __expf(mM[m2][1] - nm1);
            float rs0 = 0.f, rs1 = 0.f;
            int r = wrow + m2*16 + grp;
            #pragma unroll
            for (int nb = 0; nb < 8; nb++) {
                __half2 hp0 = __floats2half2_rn(__expf(s[m2][nb][0] - nm0),
                                                __expf(s[m2][nb][1] - nm0));
                __half2 hp1 = __floats2half2_rn(__expf(s[m2][nb][2] - nm1),
                                                __expf(s[m2][nb][3] - nm1));
                float2 f0 = __half22float2(hp0), f1 = __half22float2(hp1);
                rs0 += f0.x + f0.y; rs1 += f1.x + f1.y;
                *(__half2*)&Ps[r    *72 + nb*8 + 2*tig] = hp0;
                *(__half2*)&Ps[(r+8)*72 + nb*8 + 2*tig] = hp1;
                O[m2][nb][0] *= a0; O[m2][nb][1] *= a0;
                O[m2][nb][2] *= a1; O[m2][nb][3] *= a1;
            }
            rs0 += __shfl_xor_sync(0xffffffffu, rs0, 1);
            rs0 += __shfl_xor_sync(0xffffffffu, rs0, 2);
            rs1 += __shfl_xor_sync(0xffffffffu, rs1, 1);
            rs1 += __shfl_xor_sync(0xffffffffu, rs1, 2);
            lL[m2][0] = lL[m2][0]*a0 + rs0;
            lL[m2][1] = lL[m2][1]*a1 + rs1;
            mM[m2][0] = nm0; mM[m2][1] = nm1;
        }
        __syncwarp();     // P rows are warp-private

        // O += P @ V
        #pragma unroll
        for (int kk = 0; kk < 64; kk += 16) {
            uint32_t bb[8][2];
            #pragma unroll
            for (int nbp = 0; nbp < 4; nbp++) {
                uint32_t t4[4];
                ldsm4(t4, smb + (uint32_t)(FV3 + (nbp*16 + lr)*72 + kk + kof)*2u);
                bb[2*nbp  ][0] = t4[0]; bb[2*nbp+1][0] = t4[1];
                bb[2*nbp  ][1] = t4[2]; bb[2*nbp+1][1] = t4[3];
            }
            #pragma unroll
            for (int m2 = 0; m2 < 2; m2++) {
                uint32_t a[4];
                ldsm4(a, smb + (uint32_t)(FP3 + (wrow + m2*16 + lr)*72 + kk + kof)*2u);
                #pragma unroll
                for (int nb = 0; nb < 8; nb++)
                    mma_h(O[m2][nb], a, bb[nb]);
            }
        }
        __syncwarp();
    }

    #pragma unroll
    for (int m2 = 0; m2 < 2; m2++) {
        float i0 = 1.f/lL[m2][0], i1 = 1.f/lL[m2][1];
        int row = qt*256 + wrow + m2*16 + grp;
        #pragma unroll
        for (int nb = 0; nb < 8; nb++) {
            size_t off = (size_t)(b*NT + row)*DIM + h*HD + nb*8 + 2*tig;
            *(__half2*)(o + off)         = __floats2half2_rn(O[m2][nb][0]*i0,
                                                             O[m2][nb][1]*i0);
            *(__half2*)(o + off + 8*DIM) = __floats2half2_rn(O[m2][nb][2]*i1,
                                                             O[m2][nb][3]*i1);
        }
    }
}

// ---------------------------------------------------------------------------
// Host launcher
// ---------------------------------------------------------------------------
extern "C" void kernel_launch(void* const* d_in, const int* in_sizes, int n_in,
                              void* d_out, int out_size)
{
    const float* x       = (const float*)d_in[0];
    const float* t_emb   = (const float*)d_in[1];
    const float* norm1_g = (const float*)d_in[2];
    const float* norm1_b = (const float*)d_in[3];
    const float* Wq      = (const float*)d_in[4];
    const float* Wk      = (const float*)d_in[5];
    const float* Wv      = (const float*)d_in[6];
    const float* Wo      = (const float*)d_in[7];
    const float* norm2_g = (const float*)d_in[8];
    const float* norm2_b = (const float*)d_in[9];
    const float* W1      = (const float*)d_in[10];
    const float* W2      = (const float*)d_in[11];
    const float* ada_W   = (const float*)d_in[12];
    const float* ada_b   = (const float*)d_in[13];
    float* out = (float*)d_out;

    float *mod;
    h16 *xn, *q, *k, *v, *attn, *hbuf, *wt;
    cudaGetSymbolAddress((void**)&mod,  g_mod);
    cudaGetSymbolAddress((void**)&xn,   g_xn);
    cudaGetSymbolAddress((void**)&q,    g_q);
    cudaGetSymbolAddress((void**)&k,    g_k);
    cudaGetSymbolAddress((void**)&v,    g_v);
    cudaGetSymbolAddress((void**)&attn, g_attn);
    cudaGetSymbolAddress((void**)&hbuf, g_h);
    cudaGetSymbolAddress((void**)&wt,   g_wt);

    cudaFuncSetAttribute(gemm_h<0>, cudaFuncAttributeMaxDynamicSharedMemorySize, G_SMEM_BYTES);
    cudaFuncSetAttribute(gemm_h<1>, cudaFuncAttributeMaxDynamicSharedMemorySize, G_SMEM_BYTES);
    cudaFuncSetAttribute(gemm_h<2>, cudaFuncAttributeMaxDynamicSharedMemorySize, G_SMEM_BYTES);
    cudaFuncSetAttribute(flash_h,   cudaFuncAttributeMaxDynamicSharedMemorySize, F3_SMEM_BYTES);

    // launch 0: fused weight transpose -> fp16 [N][K]
    trans_all<<<12288, 256>>>(Wq, Wk, Wv, Wo, W1, W2, wt);
    // launch 1: adaLN modulation
    silu_mod_kernel<<<dim3(24, BT), 256>>>(t_emb, ada_W, ada_b, mod);
    // launch 2: LN1 + modulate -> fp16
    ln_mod_kernel<<<ROWS, 256>>>(x, xn, norm1_g, norm1_b, mod, 0, 1);
    // launch 3: fused QKV
    gemm_h<0><<<dim3(24, ROWS/128), 128, G_SMEM_BYTES>>>(
        xn, wt, DIM, DIM, q, k, v, nullptr, nullptr, nullptr);
    // launch 4: RoPE
    rope_kernel<<<(BT*NT*HEADS)/256, 256>>>(q, k);
    // launch 5: attention (flash v4)
    flash_h<<<dim3(NT/256, BT*HEADS), 256, F3_SMEM_BYTES>>>(q, k, v, attn);
    // launch 6: out proj + gated residual (gate_msa = chunk 2) -> d_out
    gemm_h<2><<<dim3(8, ROWS/128), 128, G_SMEM_BYTES>>>(
        attn, wt + W_O, DIM, DIM, nullptr, nullptr, nullptr,
        out, mod + 2*DIM, x);
    // launch 7: LN2 + modulate -> fp16
    ln_mod_kernel<<<ROWS, 256>>>(out, xn, norm2_g, norm2_b, mod, 3, 4);
    // launch 8: MLP up + exact GELU -> fp16
    gemm_h<1><<<dim3(32, ROWS/128), 128, G_SMEM_BYTES>>>(
        xn, wt + W_1, DIM, MLPD, hbuf, nullptr, nullptr,
        nullptr, nullptr, nullptr);
    // launch 9: MLP down + gated residual (gate_mlp = chunk 5) -> d_out
    gemm_h<2><<<dim3(8, ROWS/128), 128, G_SMEM_BYTES>>>(
        hbuf, wt + W_2, MLPD, DIM, nullptr, nullptr, nullptr,
        out, mod + 5*DIM, out);
}